// round 17
// baseline (speedup 1.0000x reference)
#include <cuda_runtime.h>
#include <cuda_bf16.h>

#define BATCH     1000000
#define FEAT      128
#define NCLASS    1000
#define NTHREADS  256
#define NBLOCKS   1184                      // 148 SMs * 8 blocks -> one full wave at 32 regs
#define WARPS_PER_BLOCK (NTHREADS / 32)
#define NWARPS    (NBLOCKS * WARPS_PER_BLOCK)   // 9472
#define TILE_ROWS 4
#define NTILES    (BATCH / TILE_ROWS)       // 250000 tiles, 27 rounds, 97.8% utilization

// Per-block partial sums (every block writes its slot every launch -> no zeroing).
__device__ float g_partials[NBLOCKS];
// Ticket counter for last-block-done reduction; reset by the last block each launch.
__device__ int g_count = 0;

__device__ __forceinline__ float warp_sum(float s) {
    #pragma unroll
    for (int o = 16; o; o >>= 1) s += __shfl_xor_sync(0xffffffffu, s, o);
    return s;
}

// 256-bit streaming load (x: read once, evict-streaming).
__device__ __forceinline__ void ldg256_cs(const float* p, float* v) {
    asm volatile("ld.global.cs.v8.f32 {%0,%1,%2,%3,%4,%5,%6,%7}, [%8];"
                 : "=f"(v[0]), "=f"(v[1]), "=f"(v[2]), "=f"(v[3]),
                   "=f"(v[4]), "=f"(v[5]), "=f"(v[6]), "=f"(v[7])
                 : "l"(p));
}
// 256-bit non-coherent load (centers: hot 512 KB table).
__device__ __forceinline__ void ldg256_nc(const float* p, float* v) {
    asm volatile("ld.global.nc.v8.f32 {%0,%1,%2,%3,%4,%5,%6,%7}, [%8];"
                 : "=f"(v[0]), "=f"(v[1]), "=f"(v[2]), "=f"(v[3]),
                   "=f"(v[4]), "=f"(v[5]), "=f"(v[6]), "=f"(v[7])
                 : "l"(p));
}

__global__ __launch_bounds__(NTHREADS, 8) void hinge_fused_kernel(
    const float* __restrict__ x,
    const int* __restrict__ labels,
    const float* __restrict__ centers,
    float* __restrict__ out)
{
    const int lane = threadIdx.x & 31;
    const int wid  = threadIdx.x >> 5;
    const int gw   = blockIdx.x * WARPS_PER_BLOCK + wid;

    // Half-warp-per-row: 16 lanes x 8 floats cover one full 512B row.
    const int half = lane >> 4;     // 0 or 1: which row of the pair
    const int hl   = lane & 15;     // lane within half -> 32B chunk index

    const float4* __restrict__ c4 = reinterpret_cast<const float4*>(centers);

    // margin = ||centers[0] - centers[1]|| / 10 (tiny, L1-hit)
    float4 ca = __ldg(&c4[lane]);
    float4 cb = __ldg(&c4[32 + lane]);
    float md0 = ca.x - cb.x, md1 = ca.y - cb.y, md2 = ca.z - cb.z, md3 = ca.w - cb.w;
    const float margin = sqrtf(warp_sum(md0*md0 + md1*md1 + md2*md2 + md3*md3)) * 0.1f;

    float acc = 0.0f;   // 16x-replicated hinge sums; rescaled by 1/16 at the end

    // Proven schedule: stride-distributed 4-row tiles. Per tile:
    //   1 label sector LDG, then 2 pairs x (one 256-bit x load + one 256-bit
    //   center gather per lane) -- each x instruction fetches 2 complete rows
    //   (8 x 128B lines issued per instruction vs 4 with float4).
    for (unsigned t = gw; t < NTILES; t += NWARPS) {
        const unsigned tbase = t * (unsigned)TILE_ROWS;
        const int mylab = __ldcs(&labels[tbase + (lane & 3)]);  // one 16B sector

        #pragma unroll
        for (int k = 0; k < TILE_ROWS / 2; k++) {
            // This lane's row: tbase + 2k + half. Label via per-lane shuffle.
            const int lab = __shfl_sync(0xffffffffu, mylab, 2 * k + half);

            float xv[8], cv[8];
            ldg256_cs(x + (size_t)(tbase + 2u * k + (unsigned)half) * 128u + hl * 8u, xv);
            ldg256_nc(centers + (size_t)(unsigned)lab * 128u + hl * 8u, cv);

            float s = 0.0f;
            #pragma unroll
            for (int i = 0; i < 8; i++) {
                float d = xv[i] - cv[i];
                s += d * d;
            }

            // 4 butterflies within the 16-lane half finish the row.
            // Lanes 0-15 -> hinge(row 2k), lanes 16-31 -> hinge(row 2k+1),
            // each replicated x16.
            #pragma unroll
            for (int o = 8; o; o >>= 1) s += __shfl_xor_sync(0xffffffffu, s, o);
            acc += fmaxf(s - margin, 0.0f);
        }
    }

    // warp_sum(acc) = 16 * (true warp hinge sum); exact 1/16 rescale.
    const float wacc = warp_sum(acc) * 0.0625f;

    // Block reduce.
    __shared__ float smem[WARPS_PER_BLOCK];
    __shared__ bool is_last;
    if (lane == 0) smem[wid] = wacc;
    __syncthreads();
    if (threadIdx.x == 0) {
        float s = 0.0f;
        #pragma unroll
        for (int i = 0; i < WARPS_PER_BLOCK; i++) s += smem[i];
        g_partials[blockIdx.x] = s;
        __threadfence();
        int ticket = atomicAdd(&g_count, 1);
        is_last = (ticket == NBLOCKS - 1);
    }
    __syncthreads();

    // Last block reduces all partials (f64, fixed order) and writes the scalar.
    if (is_last) {
        __shared__ double sm[NTHREADS];
        double s = 0.0;
        for (int i = threadIdx.x; i < NBLOCKS; i += NTHREADS)
            s += (double)g_partials[i];
        sm[threadIdx.x] = s;
        __syncthreads();
        #pragma unroll
        for (int o = NTHREADS / 2; o; o >>= 1) {
            if (threadIdx.x < o) sm[threadIdx.x] += sm[threadIdx.x + o];
            __syncthreads();
        }
        if (threadIdx.x == 0) {
            out[0] = (float)(sm[0] / (4.0 * (double)BATCH));
            g_count = 0;   // reset for next launch / graph replay
        }
    }
}

extern "C" void kernel_launch(void* const* d_in, const int* in_sizes, int n_in,
                              void* d_out, int out_size)
{
    const float* x       = (const float*)d_in[0];   // [1e6, 128] f32
    const int*   labels  = (const int*)  d_in[1];   // [1e6] i32
    const float* centers = (const float*)d_in[2];   // [1000, 128] f32
    float*       out     = (float*)d_out;           // scalar f32

    hinge_fused_kernel<<<NBLOCKS, NTHREADS>>>(x, labels, centers, out);
}